// round 3
// baseline (speedup 1.0000x reference)
#include <cuda_runtime.h>
#include <math.h>

#define NKEYS 13294
#define BATCH 2
#define EMB   256
#define NHEAD 8
#define HDIM  32
#define NLVL  4
#define NPTS  4
#define FFN   1024
#define ROWS  (BATCH*NKEYS)   // 26588
#define LN_EPS 1e-5f

// ---------------- scratch (device globals; no allocation allowed) ----------
__device__ float g_X  [ROWS*EMB];
__device__ float g_X1 [ROWS*EMB];
__device__ float g_V  [ROWS*EMB];
__device__ float g_OFF[ROWS*EMB];
__device__ float g_AW [ROWS*(NHEAD*NLVL*NPTS)];   // 128 per row
__device__ float g_ATT[ROWS*EMB];
__device__ float g_TMP[ROWS*EMB];
__device__ float g_HID[ROWS*FFN];

// ---------------- tiled fp32 GEMM: C = A(MxK) @ W(KxN) + bias, opt ReLU ----
// BM=128, BN=64, BK=16, 256 threads, 8x4 per-thread tile.
template<bool RELU>
__global__ __launch_bounds__(256)
void gemm_kernel(const float* __restrict__ A, const float* __restrict__ W,
                 const float* __restrict__ bias, float* __restrict__ C,
                 int M, int N, int K)
{
    __shared__ float As[16][132];   // [k][m], padded row (528B, 16B-aligned)
    __shared__ float Bs[16][64];    // [k][n]

    const int bm = blockIdx.y * 128;
    const int bn = blockIdx.x * 64;
    const int tid = threadIdx.x;
    const int tx = tid & 15;        // n-dir: 16 threads * 4 cols
    const int ty = tid >> 4;        // m-dir: 16 threads * 8 rows

    float acc[8][4];
#pragma unroll
    for (int i = 0; i < 8; i++)
#pragma unroll
        for (int j = 0; j < 4; j++) acc[i][j] = 0.f;

    for (int k0 = 0; k0 < K; k0 += 16) {
        // load A tile (128x16), transposed into As[k][m]; 2 float4 per thread
#pragma unroll
        for (int i = 0; i < 2; i++) {
            int s  = tid * 2 + i;           // 0..511 float4 slots
            int r  = s >> 2;                // row within tile (0..127)
            int kc = (s & 3) * 4;           // k within tile
            int grow = bm + r;
            float4 v = make_float4(0.f, 0.f, 0.f, 0.f);
            if (grow < M)
                v = *(const float4*)&A[(size_t)grow * K + k0 + kc];
            As[kc + 0][r] = v.x;
            As[kc + 1][r] = v.y;
            As[kc + 2][r] = v.z;
            As[kc + 3][r] = v.w;
        }
        // load B tile (16x64); 1 float4 per thread
        {
            int r = tid >> 4;
            int c = (tid & 15) * 4;
            float4 v = *(const float4*)&W[(size_t)(k0 + r) * N + bn + c];
            *(float4*)&Bs[r][c] = v;
        }
        __syncthreads();

#pragma unroll
        for (int kk = 0; kk < 16; kk++) {
            float a[8];
            float4 b0 = *(const float4*)&Bs[kk][tx * 4];
#pragma unroll
            for (int i = 0; i < 8; i++) a[i] = As[kk][ty * 8 + i];
#pragma unroll
            for (int i = 0; i < 8; i++) {
                acc[i][0] = fmaf(a[i], b0.x, acc[i][0]);
                acc[i][1] = fmaf(a[i], b0.y, acc[i][1]);
                acc[i][2] = fmaf(a[i], b0.z, acc[i][2]);
                acc[i][3] = fmaf(a[i], b0.w, acc[i][3]);
            }
        }
        __syncthreads();
    }

    float4 bia = *(const float4*)&bias[bn + tx * 4];
#pragma unroll
    for (int i = 0; i < 8; i++) {
        int grow = bm + ty * 8 + i;
        if (grow < M) {
            float4 o;
            o.x = acc[i][0] + bia.x;
            o.y = acc[i][1] + bia.y;
            o.z = acc[i][2] + bia.z;
            o.w = acc[i][3] + bia.w;
            if (RELU) {
                o.x = fmaxf(o.x, 0.f); o.y = fmaxf(o.y, 0.f);
                o.z = fmaxf(o.z, 0.f); o.w = fmaxf(o.w, 0.f);
            }
            *(float4*)&C[(size_t)grow * N + bn + tx * 4] = o;
        }
    }
}

// ---------------- multiscale deformable attention -------------------------
// one warp per (b,n,head); lane = channel (HD=32) -> every gather is a
// coalesced 128B load from the value tensor (27 MB, L2-resident).
__global__ __launch_bounds__(256)
void deform_attn_kernel(const float* __restrict__ V, const float* __restrict__ OFF,
                        const float* __restrict__ AWL, const float* __restrict__ REF,
                        float* __restrict__ OUT)
{
    const int lvlH[4]     = {100, 50, 25, 13};
    const int lvlW[4]     = {100, 50, 25, 13};
    const int lvlStart[4] = {0, 10000, 12500, 13125};

    const int bn   = blockIdx.x;            // 0 .. ROWS-1
    const int head = threadIdx.x >> 5;
    const int lane = threadIdx.x & 31;
    const int b    = bn / NKEYS;

    // softmax over 16 attention logits (redundant per lane; L1 broadcast)
    const float* awp = AWL + ((size_t)bn * NHEAD + head) * 16;
    float lg[16];
    float mx = -1e30f;
#pragma unroll
    for (int i = 0; i < 16; i++) { lg[i] = awp[i]; mx = fmaxf(mx, lg[i]); }
    float s = 0.f;
#pragma unroll
    for (int i = 0; i < 16; i++) { lg[i] = __expf(lg[i] - mx); s += lg[i]; }
    const float inv = 1.f / s;

    const float* offp = OFF + (size_t)bn * EMB + head * (NLVL * NPTS * 2); // 32 floats
    const float* refp = REF + (size_t)bn * (NLVL * 2);

    float acc = 0.f;
#pragma unroll
    for (int l = 0; l < NLVL; l++) {
        const int h = lvlH[l], w = lvlW[l], start = lvlStart[l];
        const float rx = refp[l * 2 + 0];
        const float ry = refp[l * 2 + 1];
        const float* vbase = V + ((size_t)(b * NKEYS + start) * NHEAD + head) * HDIM + lane;
        const size_t kstride = (size_t)NHEAD * HDIM;   // 256 floats per key
#pragma unroll
        for (int p = 0; p < NPTS; p++) {
            const float ox = offp[(l * 4 + p) * 2 + 0];
            const float oy = offp[(l * 4 + p) * 2 + 1];
            const float x = rx * (float)w + ox - 0.5f;
            const float y = ry * (float)h + oy - 0.5f;
            const float xf = floorf(x), yf = floorf(y);
            const int x0 = (int)xf, y0 = (int)yf;
            const float lx = x - xf, ly = y - yf;
            const float aw  = lg[l * 4 + p] * inv;
            const float w00 = (1.f - lx) * (1.f - ly) * aw;
            const float w01 = lx * (1.f - ly) * aw;
            const float w10 = (1.f - lx) * ly * aw;
            const float w11 = lx * ly * aw;
            const bool xin0 = (x0 >= 0) & (x0 < w);
            const bool xin1 = (x0 + 1 >= 0) & (x0 + 1 < w);
            if (y0 >= 0 && y0 < h) {
                const size_t rowo = (size_t)(y0 * w);
                if (xin0) acc = fmaf(w00, vbase[(rowo + x0) * kstride], acc);
                if (xin1) acc = fmaf(w01, vbase[(rowo + x0 + 1) * kstride], acc);
            }
            if (y0 + 1 >= 0 && y0 + 1 < h) {
                const size_t rowo = (size_t)((y0 + 1) * w);
                if (xin0) acc = fmaf(w10, vbase[(rowo + x0) * kstride], acc);
                if (xin1) acc = fmaf(w11, vbase[(rowo + x0 + 1) * kstride], acc);
            }
        }
    }
    OUT[(size_t)bn * EMB + head * HDIM + lane] = acc;
}

// ---------------- fused residual-add + LayerNorm (warp per row, E=256) -----
__global__ __launch_bounds__(256)
void add_ln_kernel(const float* __restrict__ X, const float* __restrict__ R,
                   const float* __restrict__ gam, const float* __restrict__ bet,
                   float* __restrict__ OUT, int rows)
{
    const int row  = blockIdx.x * 8 + (threadIdx.x >> 5);
    if (row >= rows) return;
    const int lane = threadIdx.x & 31;

    const float4* xp = (const float4*)(X + (size_t)row * EMB);
    const float4* rp = (const float4*)(R + (size_t)row * EMB);

    float v[8];
    float s = 0.f, ss = 0.f;
#pragma unroll
    for (int i = 0; i < 2; i++) {
        float4 a = xp[lane + i * 32];
        float4 r = rp[lane + i * 32];
        float t0 = a.x + r.x, t1 = a.y + r.y, t2 = a.z + r.z, t3 = a.w + r.w;
        v[i * 4 + 0] = t0; v[i * 4 + 1] = t1; v[i * 4 + 2] = t2; v[i * 4 + 3] = t3;
        s  += t0 + t1 + t2 + t3;
        ss += t0 * t0 + t1 * t1 + t2 * t2 + t3 * t3;
    }
#pragma unroll
    for (int o = 16; o; o >>= 1) {
        s  += __shfl_xor_sync(0xffffffffu, s,  o);
        ss += __shfl_xor_sync(0xffffffffu, ss, o);
    }
    const float mean = s * (1.f / 256.f);
    const float var  = ss * (1.f / 256.f) - mean * mean;
    const float rstd = rsqrtf(var + LN_EPS);

    float4* op = (float4*)(OUT + (size_t)row * EMB);
    const float4* gp = (const float4*)gam;
    const float4* bp = (const float4*)bet;
#pragma unroll
    for (int i = 0; i < 2; i++) {
        float4 g = gp[lane + i * 32];
        float4 bb = bp[lane + i * 32];
        float4 o;
        o.x = (v[i * 4 + 0] - mean) * rstd * g.x + bb.x;
        o.y = (v[i * 4 + 1] - mean) * rstd * g.y + bb.y;
        o.z = (v[i * 4 + 2] - mean) * rstd * g.z + bb.z;
        o.w = (v[i * 4 + 3] - mean) * rstd * g.w + bb.w;
        op[lane + i * 32] = o;
    }
}

// ---------------- host orchestration --------------------------------------
static inline void gemm(const float* A, const float* W, const float* bias,
                        float* C, int M, int N, int K, bool relu)
{
    dim3 grid(N / 64, (M + 127) / 128);
    if (relu) gemm_kernel<true ><<<grid, 256>>>(A, W, bias, C, M, N, K);
    else      gemm_kernel<false><<<grid, 256>>>(A, W, bias, C, M, N, K);
}

extern "C" void kernel_launch(void* const* d_in, const int* in_sizes, int n_in,
                              void* d_out, int out_size)
{
    const float* src  = (const float*)d_in[0];
    const float* ref  = (const float*)d_in[1];
    // d_in[2] spatial_shapes, d_in[3] level_start_index: hardcoded
    const float* Woff = (const float*)d_in[4];
    const float* boff = (const float*)d_in[5];
    const float* Waw  = (const float*)d_in[6];
    const float* baw  = (const float*)d_in[7];
    const float* Wv   = (const float*)d_in[8];
    const float* bv   = (const float*)d_in[9];
    const float* Wo   = (const float*)d_in[10];
    const float* bo   = (const float*)d_in[11];
    const float* g1   = (const float*)d_in[12];
    const float* b1   = (const float*)d_in[13];
    const float* Wf1  = (const float*)d_in[14];
    const float* bf1  = (const float*)d_in[15];
    const float* Wf2  = (const float*)d_in[16];
    const float* bf2  = (const float*)d_in[17];
    const float* g2   = (const float*)d_in[18];
    const float* b2   = (const float*)d_in[19];
    float* out = (float*)d_out;

    float *X, *X1, *V, *OFF, *AW, *ATT, *TMP, *HID;
    cudaGetSymbolAddress((void**)&X,   g_X);
    cudaGetSymbolAddress((void**)&X1,  g_X1);
    cudaGetSymbolAddress((void**)&V,   g_V);
    cudaGetSymbolAddress((void**)&OFF, g_OFF);
    cudaGetSymbolAddress((void**)&AW,  g_AW);
    cudaGetSymbolAddress((void**)&ATT, g_ATT);
    cudaGetSymbolAddress((void**)&TMP, g_TMP);
    cudaGetSymbolAddress((void**)&HID, g_HID);

    const float* xin = src;
    for (int layer = 0; layer < 6; layer++) {
        gemm(xin, Wv,   bv,   V,   ROWS, 256,  256, false);
        gemm(xin, Woff, boff, OFF, ROWS, 256,  256, false);
        gemm(xin, Waw,  baw,  AW,  ROWS, 128,  256, false);
        deform_attn_kernel<<<ROWS, 256>>>(V, OFF, AW, ref, ATT);
        gemm(ATT, Wo, bo, TMP, ROWS, 256, 256, false);
        add_ln_kernel<<<(ROWS + 7) / 8, 256>>>(xin, TMP, g1, b1, X1, ROWS);
        gemm(X1,  Wf1, bf1, HID, ROWS, 1024, 256,  true);
        gemm(HID, Wf2, bf2, TMP, ROWS, 256,  1024, false);
        float* xout = (layer == 5) ? out : X;
        add_ln_kernel<<<(ROWS + 7) / 8, 256>>>(X1, TMP, g2, b2, xout, ROWS);
        xin = X;
    }
}

// round 5
// speedup vs baseline: 1.0007x; 1.0007x over previous
#include <cuda_runtime.h>
#include <math.h>

#define NKEYS 13294
#define BATCH 2
#define EMB   256
#define NHEAD 8
#define HDIM  32
#define NLVL  4
#define NPTS  4
#define FFN   1024
#define ROWS  (BATCH*NKEYS)   // 26588
#define LN_EPS 1e-5f

// ---------------- scratch (device globals; no allocation allowed) ----------
__device__ float g_X  [ROWS*EMB];
__device__ float g_X1 [ROWS*EMB];
__device__ float g_V  [ROWS*EMB];
__device__ float g_OFF[ROWS*EMB];
__device__ float g_AW [ROWS*(NHEAD*NLVL*NPTS)];   // 128 per row
__device__ float g_ATT[ROWS*EMB];
__device__ float g_TMP[ROWS*EMB];
__device__ float g_HID[ROWS*FFN];

// ---------------- tiled fp32 GEMM: C = A(MxK) @ W(KxN) + bias, opt ReLU ----
// BM=128, BN=64, BK=16, 256 threads, 8x4 per-thread tile.
template<bool RELU>
__global__ __launch_bounds__(256)
void gemm_kernel(const float* __restrict__ A, const float* __restrict__ W,
                 const float* __restrict__ bias, float* __restrict__ C,
                 int M, int N, int K)
{
    __shared__ float As[16][132];   // [k][m], padded row (528B, 16B-aligned)
    __shared__ float Bs[16][64];    // [k][n]

    const int bm = blockIdx.y * 128;
    const int bn = blockIdx.x * 64;
    const int tid = threadIdx.x;
    const int tx = tid & 15;        // n-dir: 16 threads * 4 cols
    const int ty = tid >> 4;        // m-dir: 16 threads * 8 rows

    float acc[8][4];
#pragma unroll
    for (int i = 0; i < 8; i++)
#pragma unroll
        for (int j = 0; j < 4; j++) acc[i][j] = 0.f;

    for (int k0 = 0; k0 < K; k0 += 16) {
        // load A tile (128x16), transposed into As[k][m]; 2 float4 per thread
#pragma unroll
        for (int i = 0; i < 2; i++) {
            int s  = tid * 2 + i;           // 0..511 float4 slots
            int r  = s >> 2;                // row within tile (0..127)
            int kc = (s & 3) * 4;           // k within tile
            int grow = bm + r;
            float4 v = make_float4(0.f, 0.f, 0.f, 0.f);
            if (grow < M)
                v = *(const float4*)&A[(size_t)grow * K + k0 + kc];
            As[kc + 0][r] = v.x;
            As[kc + 1][r] = v.y;
            As[kc + 2][r] = v.z;
            As[kc + 3][r] = v.w;
        }
        // load B tile (16x64); 1 float4 per thread
        {
            int r = tid >> 4;
            int c = (tid & 15) * 4;
            float4 v = *(const float4*)&W[(size_t)(k0 + r) * N + bn + c];
            *(float4*)&Bs[r][c] = v;
        }
        __syncthreads();

#pragma unroll
        for (int kk = 0; kk < 16; kk++) {
            float a[8];
            float4 b0 = *(const float4*)&Bs[kk][tx * 4];
#pragma unroll
            for (int i = 0; i < 8; i++) a[i] = As[kk][ty * 8 + i];
#pragma unroll
            for (int i = 0; i < 8; i++) {
                acc[i][0] = fmaf(a[i], b0.x, acc[i][0]);
                acc[i][1] = fmaf(a[i], b0.y, acc[i][1]);
                acc[i][2] = fmaf(a[i], b0.z, acc[i][2]);
                acc[i][3] = fmaf(a[i], b0.w, acc[i][3]);
            }
        }
        __syncthreads();
    }

    float4 bia = *(const float4*)&bias[bn + tx * 4];
#pragma unroll
    for (int i = 0; i < 8; i++) {
        int grow = bm + ty * 8 + i;
        if (grow < M) {
            float4 o;
            o.x = acc[i][0] + bia.x;
            o.y = acc[i][1] + bia.y;
            o.z = acc[i][2] + bia.z;
            o.w = acc[i][3] + bia.w;
            if (RELU) {
                o.x = fmaxf(o.x, 0.f); o.y = fmaxf(o.y, 0.f);
                o.z = fmaxf(o.z, 0.f); o.w = fmaxf(o.w, 0.f);
            }
            *(float4*)&C[(size_t)grow * N + bn + tx * 4] = o;
        }
    }
}

// ---------------- multiscale deformable attention -------------------------
// one warp per (b,n,head); lane = channel (HD=32) -> every gather is a
// coalesced 128B load from the value tensor (27 MB, L2-resident).
__global__ __launch_bounds__(256)
void deform_attn_kernel(const float* __restrict__ V, const float* __restrict__ OFF,
                        const float* __restrict__ AWL, const float* __restrict__ REF,
                        float* __restrict__ OUT)
{
    const int lvlH[4]     = {100, 50, 25, 13};
    const int lvlW[4]     = {100, 50, 25, 13};
    const int lvlStart[4] = {0, 10000, 12500, 13125};

    const int bn   = blockIdx.x;            // 0 .. ROWS-1
    const int head = threadIdx.x >> 5;
    const int lane = threadIdx.x & 31;
    const int b    = bn / NKEYS;

    // softmax over 16 attention logits (redundant per lane; L1 broadcast)
    const float* awp = AWL + ((size_t)bn * NHEAD + head) * 16;
    float lg[16];
    float mx = -1e30f;
#pragma unroll
    for (int i = 0; i < 16; i++) { lg[i] = awp[i]; mx = fmaxf(mx, lg[i]); }
    float s = 0.f;
#pragma unroll
    for (int i = 0; i < 16; i++) { lg[i] = __expf(lg[i] - mx); s += lg[i]; }
    const float inv = 1.f / s;

    const float* offp = OFF + (size_t)bn * EMB + head * (NLVL * NPTS * 2); // 32 floats
    const float* refp = REF + (size_t)bn * (NLVL * 2);

    float acc = 0.f;
#pragma unroll
    for (int l = 0; l < NLVL; l++) {
        const int h = lvlH[l], w = lvlW[l], start = lvlStart[l];
        const float rx = refp[l * 2 + 0];
        const float ry = refp[l * 2 + 1];
        const float* vbase = V + ((size_t)(b * NKEYS + start) * NHEAD + head) * HDIM + lane;
        const size_t kstride = (size_t)NHEAD * HDIM;   // 256 floats per key
#pragma unroll
        for (int p = 0; p < NPTS; p++) {
            const float ox = offp[(l * 4 + p) * 2 + 0];
            const float oy = offp[(l * 4 + p) * 2 + 1];
            const float x = rx * (float)w + ox - 0.5f;
            const float y = ry * (float)h + oy - 0.5f;
            const float xf = floorf(x), yf = floorf(y);
            const int x0 = (int)xf, y0 = (int)yf;
            const float lx = x - xf, ly = y - yf;
            const float aw  = lg[l * 4 + p] * inv;
            const float w00 = (1.f - lx) * (1.f - ly) * aw;
            const float w01 = lx * (1.f - ly) * aw;
            const float w10 = (1.f - lx) * ly * aw;
            const float w11 = lx * ly * aw;
            const bool xin0 = (x0 >= 0) & (x0 < w);
            const bool xin1 = (x0 + 1 >= 0) & (x0 + 1 < w);
            if (y0 >= 0 && y0 < h) {
                const size_t rowo = (size_t)(y0 * w);
                if (xin0) acc = fmaf(w00, vbase[(rowo + x0) * kstride], acc);
                if (xin1) acc = fmaf(w01, vbase[(rowo + x0 + 1) * kstride], acc);
            }
            if (y0 + 1 >= 0 && y0 + 1 < h) {
                const size_t rowo = (size_t)((y0 + 1) * w);
                if (xin0) acc = fmaf(w10, vbase[(rowo + x0) * kstride], acc);
                if (xin1) acc = fmaf(w11, vbase[(rowo + x0 + 1) * kstride], acc);
            }
        }
    }
    OUT[(size_t)bn * EMB + head * HDIM + lane] = acc;
}

// ---------------- fused residual-add + LayerNorm (warp per row, E=256) -----
__global__ __launch_bounds__(256)
void add_ln_kernel(const float* __restrict__ X, const float* __restrict__ R,
                   const float* __restrict__ gam, const float* __restrict__ bet,
                   float* __restrict__ OUT, int rows)
{
    const int row  = blockIdx.x * 8 + (threadIdx.x >> 5);
    if (row >= rows) return;
    const int lane = threadIdx.x & 31;

    const float4* xp = (const float4*)(X + (size_t)row * EMB);
    const float4* rp = (const float4*)(R + (size_t)row * EMB);

    float v[8];
    float s = 0.f, ss = 0.f;
#pragma unroll
    for (int i = 0; i < 2; i++) {
        float4 a = xp[lane + i * 32];
        float4 r = rp[lane + i * 32];
        float t0 = a.x + r.x, t1 = a.y + r.y, t2 = a.z + r.z, t3 = a.w + r.w;
        v[i * 4 + 0] = t0; v[i * 4 + 1] = t1; v[i * 4 + 2] = t2; v[i * 4 + 3] = t3;
        s  += t0 + t1 + t2 + t3;
        ss += t0 * t0 + t1 * t1 + t2 * t2 + t3 * t3;
    }
#pragma unroll
    for (int o = 16; o; o >>= 1) {
        s  += __shfl_xor_sync(0xffffffffu, s,  o);
        ss += __shfl_xor_sync(0xffffffffu, ss, o);
    }
    const float mean = s * (1.f / 256.f);
    const float var  = ss * (1.f / 256.f) - mean * mean;
    const float rstd = rsqrtf(var + LN_EPS);

    float4* op = (float4*)(OUT + (size_t)row * EMB);
    const float4* gp = (const float4*)gam;
    const float4* bp = (const float4*)bet;
#pragma unroll
    for (int i = 0; i < 2; i++) {
        float4 g = gp[lane + i * 32];
        float4 bb = bp[lane + i * 32];
        float4 o;
        o.x = (v[i * 4 + 0] - mean) * rstd * g.x + bb.x;
        o.y = (v[i * 4 + 1] - mean) * rstd * g.y + bb.y;
        o.z = (v[i * 4 + 2] - mean) * rstd * g.z + bb.z;
        o.w = (v[i * 4 + 3] - mean) * rstd * g.w + bb.w;
        op[lane + i * 32] = o;
    }
}

// ---------------- host orchestration --------------------------------------
static inline void gemm(const float* A, const float* W, const float* bias,
                        float* C, int M, int N, int K, bool relu)
{
    dim3 grid(N / 64, (M + 127) / 128);
    if (relu) gemm_kernel<true ><<<grid, 256>>>(A, W, bias, C, M, N, K);
    else      gemm_kernel<false><<<grid, 256>>>(A, W, bias, C, M, N, K);
}

extern "C" void kernel_launch(void* const* d_in, const int* in_sizes, int n_in,
                              void* d_out, int out_size)
{
    const float* src  = (const float*)d_in[0];
    const float* ref  = (const float*)d_in[1];
    // d_in[2] spatial_shapes, d_in[3] level_start_index: hardcoded
    const float* Woff = (const float*)d_in[4];
    const float* boff = (const float*)d_in[5];
    const float* Waw  = (const float*)d_in[6];
    const float* baw  = (const float*)d_in[7];
    const float* Wv   = (const float*)d_in[8];
    const float* bv   = (const float*)d_in[9];
    const float* Wo   = (const float*)d_in[10];
    const float* bo   = (const float*)d_in[11];
    const float* g1   = (const float*)d_in[12];
    const float* b1   = (const float*)d_in[13];
    const float* Wf1  = (const float*)d_in[14];
    const float* bf1  = (const float*)d_in[15];
    const float* Wf2  = (const float*)d_in[16];
    const float* bf2  = (const float*)d_in[17];
    const float* g2   = (const float*)d_in[18];
    const float* b2   = (const float*)d_in[19];
    float* out = (float*)d_out;

    float *X, *X1, *V, *OFF, *AW, *ATT, *TMP, *HID;
    cudaGetSymbolAddress((void**)&X,   g_X);
    cudaGetSymbolAddress((void**)&X1,  g_X1);
    cudaGetSymbolAddress((void**)&V,   g_V);
    cudaGetSymbolAddress((void**)&OFF, g_OFF);
    cudaGetSymbolAddress((void**)&AW,  g_AW);
    cudaGetSymbolAddress((void**)&ATT, g_ATT);
    cudaGetSymbolAddress((void**)&TMP, g_TMP);
    cudaGetSymbolAddress((void**)&HID, g_HID);

    const float* xin = src;
    for (int layer = 0; layer < 6; layer++) {
        gemm(xin, Wv,   bv,   V,   ROWS, 256,  256, false);
        gemm(xin, Woff, boff, OFF, ROWS, 256,  256, false);
        gemm(xin, Waw,  baw,  AW,  ROWS, 128,  256, false);
        deform_attn_kernel<<<ROWS, 256>>>(V, OFF, AW, ref, ATT);
        gemm(ATT, Wo, bo, TMP, ROWS, 256, 256, false);
        add_ln_kernel<<<(ROWS + 7) / 8, 256>>>(xin, TMP, g1, b1, X1, ROWS);
        gemm(X1,  Wf1, bf1, HID, ROWS, 1024, 256,  true);
        gemm(HID, Wf2, bf2, TMP, ROWS, 256,  1024, false);
        float* xout = (layer == 5) ? out : X;
        add_ln_kernel<<<(ROWS + 7) / 8, 256>>>(X1, TMP, g2, b2, xout, ROWS);
        xin = X;
    }
}